// round 1
// baseline (speedup 1.0000x reference)
#include <cuda_runtime.h>
#include <cuda_bf16.h>
#include <cstdint>

#define NN   50000
#define EE   800000
#define HIN  256
#define HH   128
#define BNEPS 1e-5f

// ---------------- device scratch (no cudaMalloc allowed) ----------------
__device__ float g_deg[NN];
__device__ float g_dinv[NN];
__device__ float g_h[(size_t)NN * HH];    // layer input
__device__ float g_s[(size_t)NN * HH];    // pre-aggregation messages (read-only in edge pass)
__device__ float g_acc[(size_t)NN * HH];  // aggregation accumulator (init = self-loop)
__device__ float g_sum[HIN];              // BN column sums   (zeroed by fold kernel)
__device__ float g_sumsq[HIN];            // BN column sumsq
__device__ float g_Wp[HIN * HH];          // folded weight
__device__ float g_bshift[HH];            // folded pre-aggregation bias

// ---------------- degree / norm ----------------
__global__ void k_deg_init() {
    int i = blockIdx.x * blockDim.x + threadIdx.x;
    if (i < NN) g_deg[i] = 1.0f;   // self-loop
}

__global__ void k_deg(const int* __restrict__ ei) {
    int e = blockIdx.x * blockDim.x + threadIdx.x;
    if (e < EE) atomicAdd(&g_deg[ei[e]], 1.0f);   // row = ei[0..E)
}

__global__ void k_dinv() {
    int i = blockIdx.x * blockDim.x + threadIdx.x;
    if (i < NN) g_dinv[i] = rsqrtf(g_deg[i]);
}

// ---------------- BN column stats for the raw input x (C columns) ----------------
__global__ void k_stats(const float* __restrict__ A, int C) {
    int j = threadIdx.x;             // one column per thread, C threads
    int r0 = blockIdx.x * 128;
    int rend = min(r0 + 128, NN);
    float s = 0.f, ss = 0.f;
    for (int r = r0; r < rend; r++) {
        float v = A[(size_t)r * C + j];
        s += v; ss += v * v;
    }
    atomicAdd(&g_sum[j], s);
    atomicAdd(&g_sumsq[j], ss);
}

// ---------------- fold BN into weights: W' = diag(rs*g)W ; bshift = (beta-mu*rs*g)@W ----------------
__global__ void k_fold(int K, const float* __restrict__ W,
                       const float* __restrict__ gam, const float* __restrict__ bet) {
    __shared__ float sc[HIN], sh[HIN];
    int t = threadIdx.x;             // 256 threads
    if (t < K) {
        float mu  = g_sum[t] * (1.0f / NN);
        float var = g_sumsq[t] * (1.0f / NN) - mu * mu;
        float a   = rsqrtf(var + BNEPS) * gam[t];
        sc[t] = a;
        sh[t] = bet[t] - mu * a;
    }
    __syncthreads();
    for (int idx = t; idx < K * HH; idx += 256)
        g_Wp[idx] = sc[idx / HH] * W[idx];
    if (t < HH) {
        float acc = 0.f;
        for (int k = 0; k < K; k++) acc += sh[k] * W[k * HH + t];
        g_bshift[t] = acc;
    }
    // reset stats accumulators for next layer (and next launch)
    g_sum[t] = 0.f;
    g_sumsq[t] = 0.f;
}

// ---------------- tiled SGEMM:  s = acc = ((A @ W') + bshift) * dinv[row] ----------------
// BM=128, BN=128(=HH), BK=8, 256 threads, 8x8 microtile.
__global__ void __launch_bounds__(256) k_gemm(const float* __restrict__ A, int K) {
    __shared__ float As[8][128];
    __shared__ float Bs[8][128];
    int tid  = threadIdx.x;
    int row0 = blockIdx.x * 128;
    int tm = (tid >> 4) * 8;
    int tn = (tid & 15) * 8;
    float acc[8][8];
    #pragma unroll
    for (int i = 0; i < 8; i++)
        #pragma unroll
        for (int j = 0; j < 8; j++) acc[i][j] = 0.f;

    int lm = tid >> 1;            // 0..127
    int lk = (tid & 1) * 4;       // 0 or 4
    int arow = row0 + lm;
    bool aval = arow < NN;
    int bk = tid >> 5;            // 0..7
    int bn = (tid & 31) * 4;

    for (int kt = 0; kt < K; kt += 8) {
        float4 av = make_float4(0.f, 0.f, 0.f, 0.f);
        if (aval) av = *(const float4*)(A + (size_t)arow * K + kt + lk);
        As[lk + 0][lm] = av.x; As[lk + 1][lm] = av.y;
        As[lk + 2][lm] = av.z; As[lk + 3][lm] = av.w;
        *(float4*)(&Bs[bk][bn]) = *(const float4*)(g_Wp + (size_t)(kt + bk) * HH + bn);
        __syncthreads();
        #pragma unroll
        for (int k = 0; k < 8; k++) {
            float ra[8], rb[8];
            #pragma unroll
            for (int i = 0; i < 8; i++) ra[i] = As[k][tm + i];
            #pragma unroll
            for (int j = 0; j < 8; j++) rb[j] = Bs[k][tn + j];
            #pragma unroll
            for (int i = 0; i < 8; i++)
                #pragma unroll
                for (int j = 0; j < 8; j++) acc[i][j] += ra[i] * rb[j];
        }
        __syncthreads();
    }

    #pragma unroll
    for (int i = 0; i < 8; i++) {
        int r = row0 + tm + i;
        if (r >= NN) break;
        float dv = g_dinv[r];
        #pragma unroll
        for (int j = 0; j < 8; j += 4) {
            float4 v;
            v.x = (acc[i][j + 0] + g_bshift[tn + j + 0]) * dv;
            v.y = (acc[i][j + 1] + g_bshift[tn + j + 1]) * dv;
            v.z = (acc[i][j + 2] + g_bshift[tn + j + 2]) * dv;
            v.w = (acc[i][j + 3] + g_bshift[tn + j + 3]) * dv;
            *(float4*)(g_s   + (size_t)r * HH + tn + j) = v;
            *(float4*)(g_acc + (size_t)r * HH + tn + j) = v;   // self-loop init
        }
    }
}

// ---------------- edge scatter:  acc[col] += s[row]  (128 floats/edge, warp/edge) ----------------
__global__ void __launch_bounds__(256) k_edges(const int* __restrict__ ei) {
    int widx = (blockIdx.x * blockDim.x + threadIdx.x) >> 5;
    if (widx >= EE) return;
    int lane = threadIdx.x & 31;
    int r = ei[widx];
    int c = ei[EE + widx];
    const float4* sr = (const float4*)(g_s + (size_t)r * HH);
    float4* ac = (float4*)(g_acc + (size_t)c * HH);
    float4 v = sr[lane];
    asm volatile("red.global.add.v4.f32 [%0], {%1, %2, %3, %4};"
                 :: "l"(ac + lane), "f"(v.x), "f"(v.y), "f"(v.z), "f"(v.w)
                 : "memory");
}

// ---------------- finalize:  out = dinv[i]*acc + b ; optionally accumulate next BN stats ----------------
__global__ void k_finalize(const float* __restrict__ bgcn, float* __restrict__ out, int do_stats) {
    int j = threadIdx.x;             // HH threads
    int r0 = blockIdx.x * 128;
    int rend = min(r0 + 128, NN);
    float b = bgcn[j];
    float s = 0.f, ss = 0.f;
    for (int r = r0; r < rend; r++) {
        float v = g_dinv[r] * g_acc[(size_t)r * HH + j] + b;
        out[(size_t)r * HH + j] = v;
        s += v; ss += v * v;
    }
    if (do_stats) {
        atomicAdd(&g_sum[j], s);
        atomicAdd(&g_sumsq[j], ss);
    }
}

// ---------------- launch ----------------
extern "C" void kernel_launch(void* const* d_in, const int* in_sizes, int n_in,
                              void* d_out, int out_size) {
    const float* x       = (const float*)d_in[0];
    const int*   ei      = (const int*)  d_in[1];
    const float* bnf_g   = (const float*)d_in[2];
    const float* bnf_b   = (const float*)d_in[3];
    const float* W_feat  = (const float*)d_in[4];
    const float* b_feat  = (const float*)d_in[5];
    const float* bn_g    = (const float*)d_in[6];
    const float* bn_b    = (const float*)d_in[7];
    const float* Ws      = (const float*)d_in[8];
    const float* bs      = (const float*)d_in[9];
    float* out = (float*)d_out;

    float* g_h_ptr;   cudaGetSymbolAddress((void**)&g_h_ptr, g_h);

    const int RB   = (NN + 127) / 128;        // 391 row blocks
    const int EB   = (EE * 32) / 256;         // 100000 edge blocks

    k_deg_init<<<(NN + 255) / 256, 256>>>();
    k_deg<<<(EE + 255) / 256, 256>>>(ei);
    k_dinv<<<(NN + 255) / 256, 256>>>();

    // feature layer: BN(256) fold + GEMM K=256 + aggregate
    k_stats<<<RB, HIN>>>(x, HIN);
    k_fold<<<1, 256>>>(HIN, W_feat, bnf_g, bnf_b);
    k_gemm<<<RB, 256>>>(x, HIN);
    k_edges<<<EB, 256>>>(ei);
    k_finalize<<<RB, HH>>>(b_feat, g_h_ptr, 1);

    // 3 GCN layers, K=128
    for (int i = 0; i < 3; i++) {
        k_fold<<<1, 256>>>(HH, Ws + (size_t)i * HH * HH, bn_g + i * HH, bn_b + i * HH);
        k_gemm<<<RB, 256>>>(g_h_ptr, HH);
        k_edges<<<EB, 256>>>(ei);
        k_finalize<<<RB, HH>>>(bs + i * HH, (i == 2) ? out : g_h_ptr, (i < 2) ? 1 : 0);
    }
}

// round 2
// speedup vs baseline: 1.6046x; 1.6046x over previous
#include <cuda_runtime.h>
#include <cuda_bf16.h>
#include <cstdint>

#define NN   50000
#define EE   800000
#define HIN  256
#define HH   128
#define BNEPS 1e-5f

// ---------------- device scratch (no cudaMalloc allowed) ----------------
__device__ int   g_degr[NN];               // out-degree counts (row side)
__device__ int   g_cnt[NN];                // in-degree counts (col side)
__device__ int   g_cursor[NN];             // fill cursors
__device__ int   g_startv[NN + 1];         // CSR offsets (by col)
__device__ int   g_csr_rows[EE];           // CSR payload: source row per edge
__device__ float g_dinv[NN];
__device__ float g_h[(size_t)NN * HH];     // layer input
__device__ float g_s[(size_t)NN * HH];     // pre-aggregation messages
__device__ float g_sum[HIN];               // BN column sums (reset by k_fold)
__device__ float g_sumsq[HIN];
__device__ float g_Wp[HIN * HH];           // folded weight
__device__ float g_bshift[HH];             // folded pre-aggregation bias

// ---------------- CSR build ----------------
__global__ void k_zero_counts() {
    int i = blockIdx.x * blockDim.x + threadIdx.x;
    if (i < NN) { g_degr[i] = 0; g_cnt[i] = 0; g_cursor[i] = 0; }
}

__global__ void k_count(const int* __restrict__ ei) {
    int e = blockIdx.x * blockDim.x + threadIdx.x;
    if (e < EE) {
        atomicAdd(&g_degr[ei[e]], 1);        // row
        atomicAdd(&g_cnt[ei[EE + e]], 1);    // col
    }
}

__global__ void k_scan() {                   // single block, 1024 threads
    __shared__ int part[1024];
    int t = threadIdx.x;
    const int per = (NN + 1023) / 1024;
    int b = t * per, e = min(b + per, NN);
    int s = 0;
    for (int i = b; i < e; i++) s += g_cnt[i];
    part[t] = s;
    __syncthreads();
    for (int off = 1; off < 1024; off <<= 1) {
        int v = (t >= off) ? part[t - off] : 0;
        __syncthreads();
        part[t] += v;
        __syncthreads();
    }
    int base = (t == 0) ? 0 : part[t - 1];
    for (int i = b; i < e; i++) { g_startv[i] = base; base += g_cnt[i]; }
    if (t == 1023) g_startv[NN] = part[1023];
}

__global__ void k_fill(const int* __restrict__ ei) {
    int e = blockIdx.x * blockDim.x + threadIdx.x;
    if (e < EE) {
        int r = ei[e], c = ei[EE + e];
        int p = atomicAdd(&g_cursor[c], 1);
        g_csr_rows[g_startv[c] + p] = r;
    }
}

__global__ void k_dinv() {
    int i = blockIdx.x * blockDim.x + threadIdx.x;
    if (i < NN) g_dinv[i] = rsqrtf((float)g_degr[i] + 1.0f);   // +1 self-loop
}

// ---------------- BN column stats (C columns) ----------------
__global__ void k_stats(const float* __restrict__ A, int C) {
    int j = threadIdx.x;
    int r0 = blockIdx.x * 128;
    int rend = min(r0 + 128, NN);
    float s = 0.f, ss = 0.f;
    for (int r = r0; r < rend; r++) {
        float v = A[(size_t)r * C + j];
        s += v; ss += v * v;
    }
    atomicAdd(&g_sum[j], s);
    atomicAdd(&g_sumsq[j], ss);
}

// ---------------- fold BN into weights ----------------
__global__ void k_fold(int K, const float* __restrict__ W,
                       const float* __restrict__ gam, const float* __restrict__ bet) {
    __shared__ float sc[HIN], sh[HIN];
    int t = threadIdx.x;             // 256 threads
    if (t < K) {
        float mu  = g_sum[t] * (1.0f / NN);
        float var = g_sumsq[t] * (1.0f / NN) - mu * mu;
        float a   = rsqrtf(var + BNEPS) * gam[t];
        sc[t] = a;
        sh[t] = bet[t] - mu * a;
    }
    __syncthreads();
    for (int idx = t; idx < K * HH; idx += 256)
        g_Wp[idx] = sc[idx / HH] * W[idx];
    if (t < HH) {
        float acc = 0.f;
        for (int k = 0; k < K; k++) acc += sh[k] * W[k * HH + t];
        g_bshift[t] = acc;
    }
    g_sum[t] = 0.f;
    g_sumsq[t] = 0.f;
}

// ---------------- tiled SGEMM: g_s = ((A @ W') + bshift) * dinv[row] ----------------
__global__ void __launch_bounds__(256) k_gemm(const float* __restrict__ A, int K) {
    __shared__ float As[8][128];
    __shared__ float Bs[8][128];
    int tid  = threadIdx.x;
    int row0 = blockIdx.x * 128;
    int tm = (tid >> 4) * 8;
    int tn = (tid & 15) * 8;
    float acc[8][8];
    #pragma unroll
    for (int i = 0; i < 8; i++)
        #pragma unroll
        for (int j = 0; j < 8; j++) acc[i][j] = 0.f;

    int lm = tid >> 1;
    int lk = (tid & 1) * 4;
    int arow = row0 + lm;
    bool aval = arow < NN;
    int bk = tid >> 5;
    int bn = (tid & 31) * 4;

    for (int kt = 0; kt < K; kt += 8) {
        float4 av = make_float4(0.f, 0.f, 0.f, 0.f);
        if (aval) av = *(const float4*)(A + (size_t)arow * K + kt + lk);
        As[lk + 0][lm] = av.x; As[lk + 1][lm] = av.y;
        As[lk + 2][lm] = av.z; As[lk + 3][lm] = av.w;
        *(float4*)(&Bs[bk][bn]) = *(const float4*)(g_Wp + (size_t)(kt + bk) * HH + bn);
        __syncthreads();
        #pragma unroll
        for (int k = 0; k < 8; k++) {
            float ra[8], rb[8];
            #pragma unroll
            for (int i = 0; i < 8; i++) ra[i] = As[k][tm + i];
            #pragma unroll
            for (int j = 0; j < 8; j++) rb[j] = Bs[k][tn + j];
            #pragma unroll
            for (int i = 0; i < 8; i++)
                #pragma unroll
                for (int j = 0; j < 8; j++) acc[i][j] += ra[i] * rb[j];
        }
        __syncthreads();
    }

    #pragma unroll
    for (int i = 0; i < 8; i++) {
        int r = row0 + tm + i;
        if (r >= NN) break;
        float dv = g_dinv[r];
        #pragma unroll
        for (int j = 0; j < 8; j += 4) {
            float4 v;
            v.x = (acc[i][j + 0] + g_bshift[tn + j + 0]) * dv;
            v.y = (acc[i][j + 1] + g_bshift[tn + j + 1]) * dv;
            v.z = (acc[i][j + 2] + g_bshift[tn + j + 2]) * dv;
            v.w = (acc[i][j + 3] + g_bshift[tn + j + 3]) * dv;
            *(float4*)(g_s + (size_t)r * HH + tn + j) = v;
        }
    }
}

// ---------------- gather-aggregate: out[c] = dinv[c]*(s[c] + sum_{r in N(c)} s[r]) + b ----------------
// one warp per node, float4 per lane (32 lanes * 16B = full 512B row)
__global__ void __launch_bounds__(256) k_gather(const float* __restrict__ bgcn,
                                                float* __restrict__ out) {
    int node = (blockIdx.x * blockDim.x + threadIdx.x) >> 5;
    if (node >= NN) return;
    int lane = threadIdx.x & 31;
    const float4* __restrict__ s4 = (const float4*)g_s;

    float4 a0 = s4[(size_t)node * 32 + lane];   // self-loop term
    float4 a1 = make_float4(0.f, 0.f, 0.f, 0.f);

    int beg = g_startv[node];
    int end = g_startv[node + 1];
    int k = beg;
    for (; k + 1 < end; k += 2) {
        int r0 = __ldg(&g_csr_rows[k]);
        int r1 = __ldg(&g_csr_rows[k + 1]);
        float4 v0 = s4[(size_t)r0 * 32 + lane];
        float4 v1 = s4[(size_t)r1 * 32 + lane];
        a0.x += v0.x; a0.y += v0.y; a0.z += v0.z; a0.w += v0.w;
        a1.x += v1.x; a1.y += v1.y; a1.z += v1.z; a1.w += v1.w;
    }
    if (k < end) {
        int r0 = __ldg(&g_csr_rows[k]);
        float4 v0 = s4[(size_t)r0 * 32 + lane];
        a0.x += v0.x; a0.y += v0.y; a0.z += v0.z; a0.w += v0.w;
    }

    float dv = g_dinv[node];
    float4 b = *(const float4*)(bgcn + lane * 4);
    float4 o;
    o.x = (a0.x + a1.x) * dv + b.x;
    o.y = (a0.y + a1.y) * dv + b.y;
    o.z = (a0.z + a1.z) * dv + b.z;
    o.w = (a0.w + a1.w) * dv + b.w;
    *(float4*)(out + (size_t)node * HH + lane * 4) = o;
}

// ---------------- launch ----------------
extern "C" void kernel_launch(void* const* d_in, const int* in_sizes, int n_in,
                              void* d_out, int out_size) {
    const float* x       = (const float*)d_in[0];
    const int*   ei      = (const int*)  d_in[1];
    const float* bnf_g   = (const float*)d_in[2];
    const float* bnf_b   = (const float*)d_in[3];
    const float* W_feat  = (const float*)d_in[4];
    const float* b_feat  = (const float*)d_in[5];
    const float* bn_g    = (const float*)d_in[6];
    const float* bn_b    = (const float*)d_in[7];
    const float* Ws      = (const float*)d_in[8];
    const float* bs      = (const float*)d_in[9];
    float* out = (float*)d_out;

    float* g_h_ptr;   cudaGetSymbolAddress((void**)&g_h_ptr, g_h);

    const int RB = (NN + 127) / 128;              // 391 row blocks
    const int GB = (NN * 32 + 255) / 256;         // gather blocks (warp/node)
    const int EB = (EE + 255) / 256;

    // CSR build (once, reused by all 4 layers)
    k_zero_counts<<<(NN + 255) / 256, 256>>>();
    k_count<<<EB, 256>>>(ei);
    k_scan<<<1, 1024>>>();
    k_fill<<<EB, 256>>>(ei);
    k_dinv<<<(NN + 255) / 256, 256>>>();

    // feature layer: BN(256) fold + GEMM K=256 + gather
    k_stats<<<RB, HIN>>>(x, HIN);
    k_fold<<<1, 256>>>(HIN, W_feat, bnf_g, bnf_b);
    k_gemm<<<RB, 256>>>(x, HIN);
    k_gather<<<GB, 256>>>(b_feat, g_h_ptr);

    // 3 GCN layers, K=128
    for (int i = 0; i < 3; i++) {
        k_stats<<<RB, HH>>>(g_h_ptr, HH);
        k_fold<<<1, 256>>>(HH, Ws + (size_t)i * HH * HH, bn_g + i * HH, bn_b + i * HH);
        k_gemm<<<RB, 256>>>(g_h_ptr, HH);
        k_gather<<<GB, 256>>>(bs + i * HH, (i == 2) ? out : g_h_ptr);
    }
}